// round 3
// baseline (speedup 1.0000x reference)
#include <cuda_runtime.h>

// ---------------------------------------------------------------------------
// LieSpline: SE(3) cubic B-spline interpolation.  B=32, N=2048, K=32.
//
// Kernel 1 (tiled): per padded delta j, compute se3_log(inv(P[j])P[j+1]) and
//   all lane-invariant precomputes for exp(w*delta), PLUS the padded base
//   pose P[j], packed as 6 float4 (96B) per delta:
//     r0: tau.xyz | nd       r1: U.xyz | 2/nd^2    r2: C1.xyz | 1/nd^3
//     r3: C2.xyz | 0         r4: pose_t.xyz | 0    r5: pose_q.xyzw
// Kernel 2: warp = (b, segment), lane = time sample.  Per step:
//   theta=w*nd; sincos(theta/2); alpha=sh^2*K2; beta=(theta-2shch)*rn3;
//   At = w*tau + alpha*C1 + beta*C2 ; Aq = (sh*U, ch); compose.
// ---------------------------------------------------------------------------

#define LS_B 32
#define LS_N 2048
#define LS_J (LS_N + 1)   // 2049 deltas per batch
#define REC 6             // float4s per delta record

__device__ float4 g_pre[LS_B * LS_J * REC];   // 6.3 MB scratch

__device__ __forceinline__ float3 f3(float x, float y, float z) {
    return make_float3(x, y, z);
}
__device__ __forceinline__ float3 cross3(const float3 a, const float3 b) {
    return make_float3(a.y * b.z - a.z * b.y,
                       a.z * b.x - a.x * b.z,
                       a.x * b.y - a.y * b.x);
}
__device__ __forceinline__ float dot3(const float3 a, const float3 b) {
    return a.x * b.x + a.y * b.y + a.z * b.z;
}
__device__ __forceinline__ float3 qrot(const float4 q, const float3 v) {
    float3 qv = f3(q.x, q.y, q.z);
    float3 t = cross3(qv, v);
    t.x *= 2.0f; t.y *= 2.0f; t.z *= 2.0f;
    float3 c = cross3(qv, t);
    return f3(v.x + q.w * t.x + c.x,
              v.y + q.w * t.y + c.y,
              v.z + q.w * t.z + c.z);
}
__device__ __forceinline__ float4 qmul(const float4 a, const float4 b) {
    return make_float4(
        a.w * b.x + a.x * b.w + a.y * b.z - a.z * b.y,
        a.w * b.y + a.y * b.w + a.z * b.x - a.x * b.z,
        a.w * b.z + a.z * b.w + a.x * b.y - a.y * b.x,
        a.w * b.w - a.x * b.x - a.y * b.y - a.z * b.z);
}

// ---------------------------------------------------------------------------
// Kernel 1: grid (9, B).  Block covers 256 deltas of one batch; poses are
// staged through shared with coalesced loads.
// ---------------------------------------------------------------------------
#define K1_ROWS 257                     // 256 deltas need 257 pose rows
__global__ void __launch_bounds__(256) k_delta(const float* __restrict__ poses) {
    __shared__ float tile[K1_ROWS * 7];
    int b  = blockIdx.y;
    int j0 = blockIdx.x * 256;
    const float* pbase = poses + (size_t)b * LS_N * 7;

    // tile[r] = input[clamp(j0-1+r, 0, N-1)]   (row-major, 7 floats/row)
    for (int t = threadIdx.x; t < K1_ROWS * 7; t += 256) {
        int r = t / 7;
        int c = t - r * 7;
        int src = j0 - 1 + r;
        src = src < 0 ? 0 : (src > LS_N - 1 ? LS_N - 1 : src);
        tile[t] = pbase[src * 7 + c];
    }
    __syncthreads();

    int j = j0 + threadIdx.x;
    if (j >= LS_J) return;
    float4* o = g_pre + ((size_t)b * LS_J + j) * REC;

    const float* pr0 = tile + threadIdx.x * 7;      // P[j]
    const float* pr1 = pr0 + 7;                      // P[j+1]
    float3 t0 = f3(pr0[0], pr0[1], pr0[2]);
    float4 q0 = make_float4(pr0[3], pr0[4], pr0[5], pr0[6]);

    // pose record (always)
    o[4] = make_float4(t0.x, t0.y, t0.z, 0.f);
    o[5] = q0;

    if (j == 0 || j == LS_N) {
        float4 z = make_float4(0.f, 0.f, 0.f, 0.f);
        o[0] = z; o[1] = z; o[2] = z; o[3] = z;
        return;
    }
    float3 t1 = f3(pr1[0], pr1[1], pr1[2]);
    float4 q1 = make_float4(pr1[3], pr1[4], pr1[5], pr1[6]);

    // rel = inv(T0) * T1
    float4 qi = make_float4(-q0.x, -q0.y, -q0.z, q0.w);
    float3 dt = f3(t1.x - t0.x, t1.y - t0.y, t1.z - t0.z);
    float3 t  = qrot(qi, dt);
    float4 q  = qmul(qi, q1);

    // so3_log(q) -> phi
    float n2 = q.x * q.x + q.y * q.y + q.z * q.z;
    bool small = n2 < 1e-12f;
    float ns = small ? 1.0f : n2;
    float rn = rsqrtf(ns);
    float n  = ns * rn;
    float factor;
    if (small) {
        float iw = __fdividef(1.0f, q.w);
        factor = 2.0f * iw - (2.0f / 3.0f) * n2 * iw * iw * iw;
    } else {
        factor = 2.0f * atan2f(n, q.w) * rn;
    }
    float3 phi = f3(factor * q.x, factor * q.y, factor * q.z);

    // jl_inv(phi, t) -> tau
    float t2 = dot3(phi, phi);
    bool sm2 = t2 < 1e-12f;
    float t2s = sm2 ? 1.0f : t2;
    float rth = rsqrtf(t2s);
    float theta = t2s * rth;
    float s, cth;
    __sincosf(theta, &s, &cth);
    float s_safe = (fabsf(s) < 1e-6f) ? 1e-6f : s;
    float c;
    if (sm2) {
        c = (1.0f / 12.0f) + t2 * (1.0f / 720.0f);
    } else {
        c = rth * rth - __fdividef(1.0f + cth, 2.0f * theta * s_safe);
    }
    float3 x1 = cross3(phi, t);
    float3 x2 = cross3(phi, x1);
    float3 tau = f3(t.x - 0.5f * x1.x + c * x2.x,
                    t.y - 0.5f * x1.y + c * x2.y,
                    t.z - 0.5f * x1.z + c * x2.z);

    // lane-invariant precompute for exp(w * (tau, phi))
    float nd2 = dot3(phi, phi);
    if (nd2 < 1e-24f) {
        o[0] = make_float4(tau.x, tau.y, tau.z, 0.f);
        float4 z = make_float4(0.f, 0.f, 0.f, 0.f);
        o[1] = z; o[2] = z; o[3] = z;
        return;
    }
    float rnd = rsqrtf(nd2);         // 1/nd
    float nd  = nd2 * rnd;           // |phi|
    float K2  = 2.0f * rnd * rnd;    // 2/nd^2
    float rn3 = rnd * rnd * rnd;     // 1/nd^3
    float3 U  = f3(phi.x * rnd, phi.y * rnd, phi.z * rnd);
    float3 C1 = cross3(phi, tau);
    float3 C2 = cross3(phi, C1);
    o[0] = make_float4(tau.x, tau.y, tau.z, nd);
    o[1] = make_float4(U.x, U.y, U.z, K2);
    o[2] = make_float4(C1.x, C1.y, C1.z, rn3);
    o[3] = make_float4(C2.x, C2.y, C2.z, 0.f);
}

// ---------------------------------------------------------------------------
// step: T <- T * exp(wk * delta)
// ---------------------------------------------------------------------------
__device__ __forceinline__ void step(float3& Tt, float4& Tq,
                                     const float4* __restrict__ p, float wk) {
    float4 a0 = p[0];   // tau, nd
    float4 a1 = p[1];   // U,   2/nd^2
    float4 a2 = p[2];   // C1,  1/nd^3
    float4 a3 = p[3];   // C2,  -
    float theta = wk * a0.w;
    float sh, ch;
    __sincosf(0.5f * theta, &sh, &ch);
    float alpha = (sh * sh) * a1.w;                // (1 - cos th)/nd^2
    float s2 = sh + sh;
    float beta = fmaf(-s2, ch, theta) * a2.w;      // (th - sin th)/nd^3
    float3 At = f3(fmaf(beta, a3.x, fmaf(alpha, a2.x, wk * a0.x)),
                   fmaf(beta, a3.y, fmaf(alpha, a2.y, wk * a0.y)),
                   fmaf(beta, a3.z, fmaf(alpha, a2.z, wk * a0.z)));
    float4 Aq = make_float4(sh * a1.x, sh * a1.y, sh * a1.z, ch);
    float3 r = qrot(Tq, At);
    Tt.x += r.x; Tt.y += r.y; Tt.z += r.z;
    Tq = qmul(Tq, Aq);
}

// ---------------------------------------------------------------------------
// Kernel 2: warp = (b, segment s), lane = time sample k (K == 32).
// ---------------------------------------------------------------------------
__global__ void __launch_bounds__(256) k_spline(const float* __restrict__ timev,
                                                float* __restrict__ out) {
    const int S = LS_N - 1;  // 2047
    int w    = threadIdx.x >> 5;
    int lane = threadIdx.x & 31;
    int pair = blockIdx.x * (blockDim.x >> 5) + w;
    if (pair >= LS_B * S) return;
    int b = pair / S;
    int s = pair - b * S;

    // spline weights for this lane's time sample
    float u  = __ldg(timev + lane);
    float u2 = u * u;
    float u3 = u2 * u;
    const float w0 = (5.0f + 3.0f * u - 3.0f * u2 + u3) * (1.0f / 6.0f);
    const float w1 = (1.0f + 3.0f * u + 3.0f * u2 - 2.0f * u3) * (1.0f / 6.0f);
    const float w2 = u3 * (1.0f / 6.0f);

    const float4* pre = g_pre + ((size_t)b * LS_J + s) * REC;

    // base pose P[s] from record s
    float4 pt = pre[4];
    float4 pq = pre[5];
    float3 Tt = f3(pt.x, pt.y, pt.z);
    float4 Tq = pq;

    step(Tt, Tq, pre,           w0);
    step(Tt, Tq, pre + REC,     w1);
    step(Tt, Tq, pre + 2 * REC, w2);

    // stage through shared; read back / store as float4 (coalesced 128B)
    __shared__ __align__(16) float sm[8 * 224];
    float* smw = sm + w * 224;
    int o7 = lane * 7;
    smw[o7 + 0] = Tt.x; smw[o7 + 1] = Tt.y; smw[o7 + 2] = Tt.z;
    smw[o7 + 3] = Tq.x; smw[o7 + 4] = Tq.y; smw[o7 + 5] = Tq.z; smw[o7 + 6] = Tq.w;
    __syncwarp();
    const float4* sm4 = (const float4*)smw;
    float4* ob4 = (float4*)(out + (size_t)pair * 224);
    ob4[lane] = sm4[lane];                     // 32 float4
    if (lane < 24) ob4[32 + lane] = sm4[32 + lane];   // remaining 24 float4
}

extern "C" void kernel_launch(void* const* d_in, const int* in_sizes, int n_in,
                              void* d_out, int out_size) {
    (void)n_in; (void)out_size;
    const float* poses = (const float*)d_in[0];
    const float* timev = (const float*)d_in[1];
    float* out = (float*)d_out;

    dim3 g1((LS_J + 255) / 256, LS_B);
    k_delta<<<g1, 256>>>(poses);

    int pairs = LS_B * (LS_N - 1);
    k_spline<<<(pairs + 7) / 8, 256>>>(timev, out);
}

// round 4
// speedup vs baseline: 1.1606x; 1.1606x over previous
#include <cuda_runtime.h>

// ---------------------------------------------------------------------------
// LieSpline: SE(3) cubic B-spline interpolation.  B=32, N=2048, K=32.
//
// Kernel 1: per padded delta j (0..N), compute se3_log(inv(P[j])P[j+1]) and
//   lane-invariant precomputes for exp(w*delta), plus the padded base pose,
//   packed as 6 float4 per record:
//     r0: tau | nd    r1: U | 2/nd^2   r2: C1 | 1/nd^3
//     r3: C2 | 0      r4: pose_t | 0   r5: pose_q
// Kernel 2: warp = (b, 2 consecutive segments), lane = time sample (K==32).
//   Loads 4 delta records + 2 poses, computes 6 independent exps
//   (6 overlapping sincos), composes two trees, stores 448 contiguous floats.
// ---------------------------------------------------------------------------

#define LS_B 32
#define LS_N 2048
#define LS_J (LS_N + 1)   // 2049 deltas per batch
#define REC 6             // float4s per delta record
#define LS_S (LS_N - 1)   // 2047 segments
#define LS_M 1024         // segment-pairs per batch (ceil(2047/2))

__device__ float4 g_pre[LS_B * LS_J * REC];   // 6.3 MB scratch

__device__ __forceinline__ float3 f3(float x, float y, float z) {
    return make_float3(x, y, z);
}
__device__ __forceinline__ float3 cross3(const float3 a, const float3 b) {
    return make_float3(a.y * b.z - a.z * b.y,
                       a.z * b.x - a.x * b.z,
                       a.x * b.y - a.y * b.x);
}
__device__ __forceinline__ float dot3(const float3 a, const float3 b) {
    return a.x * b.x + a.y * b.y + a.z * b.z;
}
__device__ __forceinline__ float3 qrot(const float4 q, const float3 v) {
    float3 qv = f3(q.x, q.y, q.z);
    float3 t = cross3(qv, v);
    t.x *= 2.0f; t.y *= 2.0f; t.z *= 2.0f;
    float3 c = cross3(qv, t);
    return f3(v.x + q.w * t.x + c.x,
              v.y + q.w * t.y + c.y,
              v.z + q.w * t.z + c.z);
}
__device__ __forceinline__ float4 qmul(const float4 a, const float4 b) {
    return make_float4(
        a.w * b.x + a.x * b.w + a.y * b.z - a.z * b.y,
        a.w * b.y + a.y * b.w + a.z * b.x - a.x * b.z,
        a.w * b.z + a.z * b.w + a.x * b.y - a.y * b.x,
        a.w * b.w - a.x * b.x - a.y * b.y - a.z * b.z);
}

// ---------------------------------------------------------------------------
// Kernel 1: per-(b, j) relative-pose log + precompute (direct loads, R2-style)
// ---------------------------------------------------------------------------
__global__ void __launch_bounds__(256) k_delta(const float* __restrict__ poses) {
    int idx = blockIdx.x * blockDim.x + threadIdx.x;
    if (idx >= LS_B * LS_J) return;
    int b = idx / LS_J;
    int j = idx - b * LS_J;
    float4* o = g_pre + (size_t)idx * REC;
    const float* pbase = poses + (size_t)b * LS_N * 7;

    // padded base pose: input[clamp(j-1, 0, N-1)]
    int pj = j > 0 ? j - 1 : 0;
    const float* pr = pbase + (size_t)pj * 7;
    float3 t0 = f3(pr[0], pr[1], pr[2]);
    float4 q0 = make_float4(pr[3], pr[4], pr[5], pr[6]);
    o[4] = make_float4(t0.x, t0.y, t0.z, 0.f);
    o[5] = q0;

    if (j == 0 || j == LS_N) {
        float4 z = make_float4(0.f, 0.f, 0.f, 0.f);
        o[0] = z; o[1] = z; o[2] = z; o[3] = z;
        return;
    }
    const float* pr1 = pr + 7;
    float3 t1 = f3(pr1[0], pr1[1], pr1[2]);
    float4 q1 = make_float4(pr1[3], pr1[4], pr1[5], pr1[6]);

    // rel = inv(T0) * T1
    float4 qi = make_float4(-q0.x, -q0.y, -q0.z, q0.w);
    float3 dt = f3(t1.x - t0.x, t1.y - t0.y, t1.z - t0.z);
    float3 t  = qrot(qi, dt);
    float4 q  = qmul(qi, q1);

    // so3_log(q) -> phi
    float n2 = q.x * q.x + q.y * q.y + q.z * q.z;
    bool small = n2 < 1e-12f;
    float ns = small ? 1.0f : n2;
    float rn = rsqrtf(ns);
    float n  = ns * rn;
    float factor;
    if (small) {
        float iw = __fdividef(1.0f, q.w);
        factor = 2.0f * iw - (2.0f / 3.0f) * n2 * iw * iw * iw;
    } else {
        factor = 2.0f * atan2f(n, q.w) * rn;
    }
    float3 phi = f3(factor * q.x, factor * q.y, factor * q.z);

    // jl_inv(phi, t) -> tau
    float t2 = dot3(phi, phi);
    bool sm2 = t2 < 1e-12f;
    float t2s = sm2 ? 1.0f : t2;
    float rth = rsqrtf(t2s);
    float theta = t2s * rth;
    float s, cth;
    __sincosf(theta, &s, &cth);
    float s_safe = (fabsf(s) < 1e-6f) ? 1e-6f : s;
    float c;
    if (sm2) {
        c = (1.0f / 12.0f) + t2 * (1.0f / 720.0f);
    } else {
        c = rth * rth - __fdividef(1.0f + cth, 2.0f * theta * s_safe);
    }
    float3 x1 = cross3(phi, t);
    float3 x2 = cross3(phi, x1);
    float3 tau = f3(t.x - 0.5f * x1.x + c * x2.x,
                    t.y - 0.5f * x1.y + c * x2.y,
                    t.z - 0.5f * x1.z + c * x2.z);

    float nd2 = dot3(phi, phi);
    if (nd2 < 1e-24f) {
        o[0] = make_float4(tau.x, tau.y, tau.z, 0.f);
        float4 z = make_float4(0.f, 0.f, 0.f, 0.f);
        o[1] = z; o[2] = z; o[3] = z;
        return;
    }
    float rnd = rsqrtf(nd2);         // 1/nd
    float nd  = nd2 * rnd;           // |phi|
    float K2  = 2.0f * rnd * rnd;    // 2/nd^2
    float rn3 = rnd * rnd * rnd;     // 1/nd^3
    float3 U  = f3(phi.x * rnd, phi.y * rnd, phi.z * rnd);
    float3 C1 = cross3(phi, tau);
    float3 C2 = cross3(phi, C1);
    o[0] = make_float4(tau.x, tau.y, tau.z, nd);
    o[1] = make_float4(U.x, U.y, U.z, K2);
    o[2] = make_float4(C1.x, C1.y, C1.z, rn3);
    o[3] = make_float4(C2.x, C2.y, C2.z, 0.f);
}

// ---------------------------------------------------------------------------
// exp(wk * delta) from a 4-float4 record
// ---------------------------------------------------------------------------
struct Xf { float3 t; float4 q; };

__device__ __forceinline__ Xf expw(const float4 a0, const float4 a1,
                                   const float4 a2, const float4 a3,
                                   float wk) {
    float theta = wk * a0.w;
    float sh, ch;
    __sincosf(0.5f * theta, &sh, &ch);
    float alpha = (sh * sh) * a1.w;                // (1 - cos th)/nd^2
    float beta = fmaf(-(sh + sh), ch, theta) * a2.w;  // (th - sin th)/nd^3
    Xf r;
    r.t = f3(fmaf(beta, a3.x, fmaf(alpha, a2.x, wk * a0.x)),
             fmaf(beta, a3.y, fmaf(alpha, a2.y, wk * a0.y)),
             fmaf(beta, a3.z, fmaf(alpha, a2.z, wk * a0.z)));
    r.q = make_float4(sh * a1.x, sh * a1.y, sh * a1.z, ch);
    return r;
}

__device__ __forceinline__ Xf compose(const Xf& P, const Xf& Q) {
    Xf r;
    float3 rt = qrot(P.q, Q.t);
    r.t = f3(P.t.x + rt.x, P.t.y + rt.y, P.t.z + rt.z);
    r.q = qmul(P.q, Q.q);
    return r;
}

// ---------------------------------------------------------------------------
// Kernel 2: warp = (b, segment pair m -> segments 2m, 2m+1), lane = sample k.
// ---------------------------------------------------------------------------
__global__ void __launch_bounds__(256) k_spline(const float* __restrict__ timev,
                                                float* __restrict__ out) {
    int w    = threadIdx.x >> 5;
    int lane = threadIdx.x & 31;
    int gp = blockIdx.x * 8 + w;
    if (gp >= LS_B * LS_M) return;
    int b = gp >> 10;            // /LS_M
    int m = gp & (LS_M - 1);
    int s0 = 2 * m;
    bool tail = (s0 + 1 >= LS_S);   // s0 == 2046: second segment is invalid

    // spline weights for this lane's time sample
    float u  = __ldg(timev + lane);
    float u2 = u * u;
    float u3 = u2 * u;
    const float w0 = (5.0f + 3.0f * u - 3.0f * u2 + u3) * (1.0f / 6.0f);
    const float w1 = (1.0f + 3.0f * u + 3.0f * u2 - 2.0f * u3) * (1.0f / 6.0f);
    const float w2 = u3 * (1.0f / 6.0f);

    const float4* base = g_pre + ((size_t)b * LS_J) * REC;
    const float4* R0 = base + (size_t)s0 * REC;
    const float4* R1 = R0 + REC;
    const float4* R2 = R0 + 2 * REC;
    int s3 = tail ? (s0 + 2) : (s0 + 3);     // dummy (unused result) on tail
    const float4* R3 = base + (size_t)s3 * REC;

    // load 4 delta records
    float4 d0a = R0[0], d0b = R0[1], d0c = R0[2], d0d = R0[3];
    float4 d1a = R1[0], d1b = R1[1], d1c = R1[2], d1d = R1[3];
    float4 d2a = R2[0], d2b = R2[1], d2c = R2[2], d2d = R2[3];
    float4 d3a = R3[0], d3b = R3[1], d3c = R3[2], d3d = R3[3];

    // 6 independent exps (6 overlapping sincos)
    Xf A0 = expw(d0a, d0b, d0c, d0d, w0);
    Xf A1 = expw(d1a, d1b, d1c, d1d, w1);
    Xf A2 = expw(d2a, d2b, d2c, d2d, w2);
    Xf B0 = expw(d1a, d1b, d1c, d1d, w0);
    Xf B1 = expw(d2a, d2b, d2c, d2d, w1);
    Xf B2 = expw(d3a, d3b, d3c, d3d, w2);

    // poses
    float4 p0t = R0[4], p0q = R0[5];
    float4 p1t = R1[4], p1q = R1[5];
    Xf P0; P0.t = f3(p0t.x, p0t.y, p0t.z); P0.q = p0q;
    Xf P1; P1.t = f3(p1t.x, p1t.y, p1t.z); P1.q = p1q;

    // tree composition: out = (P·A0)·(A1·A2)
    Xf O0 = compose(compose(P0, A0), compose(A1, A2));
    Xf O1 = compose(compose(P1, B0), compose(B1, B2));

    // stage through shared; 448 contiguous floats per warp
    __shared__ __align__(16) float sm[8 * 448];
    float* smw = sm + w * 448;
    int o7 = lane * 7;
    smw[o7 + 0] = O0.t.x; smw[o7 + 1] = O0.t.y; smw[o7 + 2] = O0.t.z;
    smw[o7 + 3] = O0.q.x; smw[o7 + 4] = O0.q.y; smw[o7 + 5] = O0.q.z; smw[o7 + 6] = O0.q.w;
    float* smw2 = smw + 224;
    smw2[o7 + 0] = O1.t.x; smw2[o7 + 1] = O1.t.y; smw2[o7 + 2] = O1.t.z;
    smw2[o7 + 3] = O1.q.x; smw2[o7 + 4] = O1.q.y; smw2[o7 + 5] = O1.q.z; smw2[o7 + 6] = O1.q.w;
    __syncwarp();

    const float4* sm4 = (const float4*)smw;
    size_t pair0 = (size_t)b * LS_S + s0;
    float4* ob4 = (float4*)(out + pair0 * 224);
    if (!tail) {
        // 112 float4 contiguous
        ob4[lane]      = sm4[lane];
        ob4[lane + 32] = sm4[lane + 32];
        ob4[lane + 64] = sm4[lane + 64];
        if (lane < 16) ob4[lane + 96] = sm4[lane + 96];
    } else {
        // only first segment valid: 56 float4
        ob4[lane] = sm4[lane];
        if (lane < 24) ob4[lane + 32] = sm4[lane + 32];
    }
}

extern "C" void kernel_launch(void* const* d_in, const int* in_sizes, int n_in,
                              void* d_out, int out_size) {
    (void)n_in; (void)out_size;
    const float* poses = (const float*)d_in[0];
    const float* timev = (const float*)d_in[1];
    float* out = (float*)d_out;

    int tot1 = LS_B * LS_J;
    k_delta<<<(tot1 + 255) / 256, 256>>>(poses);

    int tot2 = LS_B * LS_M;
    k_spline<<<(tot2 + 7) / 8, 256>>>(timev, out);
}